// round 3
// baseline (speedup 1.0000x reference)
#include <cuda_runtime.h>

// B=8, T=2048, V=1024.
// With c = idx[b,t], q_1..q_m = occurrences of c in [0..t], Cv(r) = inclusive
// prefix histogram:
//   L_t[v] = w2*( m*Cv(t) - sum_j Cv(q_j-1) ) + a0*m*[v==c]
//            + a1*#{j : q_j+1 <= t and idx(q_j+1)==v},   out = softmax(L_t)
// Prefix hists checkpointed every SEG=32 positions (u16, L2-resident).
// One block per (b, segment): processes 32 consecutive t's, row + own
// checkpoint cached in registers/smem.

namespace {
constexpr int B = 8, T = 2048, V = 1024;
constexpr int SEG = 32, NSEG = T / SEG;
constexpr int NT = 256;
constexpr int NW = NT / 32;
}

// g_cp[b][p][v] = #{s < 32*p : idx(b,s)==v}  (exclusive prefix at segment start)
__device__ unsigned short g_cp[B][NSEG][V];
__device__ unsigned short g_row[B][T];

// ---- K1: per-segment histograms (+ u16 row copy) ----
__global__ __launch_bounds__(NT) void k_seghist(const int* __restrict__ idx) {
    __shared__ int hist[V];
    const int p = blockIdx.x, b = blockIdx.y, tid = threadIdx.x;
    #pragma unroll
    for (int i = tid; i < V; i += NT) hist[i] = 0;
    __syncthreads();
    if (tid < SEG) {
        const int tok = idx[b * T + p * SEG + tid];
        g_row[b][p * SEG + tid] = (unsigned short)tok;
        atomicAdd(&hist[tok], 1);
    }
    __syncthreads();
    const int v0 = tid * 4;
    ushort4 o;
    o.x = (unsigned short)hist[v0 + 0];
    o.y = (unsigned short)hist[v0 + 1];
    o.z = (unsigned short)hist[v0 + 2];
    o.w = (unsigned short)hist[v0 + 3];
    *reinterpret_cast<ushort4*>(&g_cp[b][p][v0]) = o;
}

// ---- K2: exclusive prefix over the 64 segments, per (b, v) ----
__global__ __launch_bounds__(NT) void k_prefix() {
    const int b = blockIdx.x;
    const int v = blockIdx.y * NT + threadIdx.x;
    unsigned run = 0;
    #pragma unroll
    for (int pc = 0; pc < 4; pc++) {
        unsigned x[16];
        #pragma unroll
        for (int k = 0; k < 16; k++) x[k] = g_cp[b][pc * 16 + k][v];
        #pragma unroll
        for (int k = 0; k < 16; k++) {
            const unsigned y = run;
            run += x[k];
            g_cp[b][pc * 16 + k][v] = (unsigned short)y;
        }
    }
}

// ---- K3: one block per (b, segment); 32 t's per block ----
__global__ __launch_bounds__(NT) void k_main(const float* __restrict__ vw,
                                             float* __restrict__ out) {
    __shared__ unsigned short srow[T];    // 4 KB
    __shared__ float acc[V];              // 4 KB
    __shared__ unsigned short qlist[T];   // 4 KB (worst case all tokens equal)
    __shared__ int qcnt;
    __shared__ float rbuf[NW];

    const int p = blockIdx.x, b = blockIdx.y;
    const int tid = threadIdx.x, lane = tid & 31, warp = tid >> 5;
    const int t0 = p * SEG;
    const int v0 = tid * 4;
    const int s0 = tid * 8;

    // Row tokens: thread holds s0..s0+7 in registers, also mirrored to smem.
    const uint4 rowv = reinterpret_cast<const uint4*>(g_row[b])[tid];
    reinterpret_cast<uint4*>(srow)[tid] = rowv;
    reinterpret_cast<float4*>(acc)[tid] = make_float4(0.f, 0.f, 0.f, 0.f);
    if (tid == 0) qcnt = 0;

    unsigned tk[8];
    tk[0] = rowv.x & 0xFFFFu; tk[1] = rowv.x >> 16;
    tk[2] = rowv.y & 0xFFFFu; tk[3] = rowv.y >> 16;
    tk[4] = rowv.z & 0xFFFFu; tk[5] = rowv.z >> 16;
    tk[6] = rowv.w & 0xFFFFu; tk[7] = rowv.w >> 16;

    // This block's segment checkpoint, held in registers (constant over t-loop).
    float cp0, cp1, cp2, cp3;
    {
        const ushort4 c4 = *reinterpret_cast<const ushort4*>(&g_cp[b][p][v0]);
        cp0 = (float)c4.x; cp1 = (float)c4.y;
        cp2 = (float)c4.z; cp3 = (float)c4.w;
    }

    const float w0 = vw[0], w1 = vw[1], w2 = vw[2];
    const float a0 = w0 - w2, a1 = w1 - w2;

    __syncthreads();

    float* const orow = out + ((size_t)(b * T + t0)) * V + v0;

    for (int ti = 0; ti < SEG; ti++) {
        const int t = t0 + ti;
        const unsigned c = srow[t];

        // Enumerate occurrences of c in [0..t] from registers (order-free).
        unsigned mask = 0;
        #pragma unroll
        for (int k = 0; k < 8; k++)
            if (tk[k] == c && s0 + k <= t) mask |= 1u << k;
        if (mask) {
            int base = atomicAdd(&qcnt, __popc(mask));
            while (mask) {
                const int k = __ffs(mask) - 1;
                mask &= mask - 1;
                qlist[base++] = (unsigned short)(s0 + k);
            }
        }
        __syncthreads();                      // qlist / qcnt ready
        const int m = qcnt;
        const float fm = (float)m;

        // Register part: w2 coefficient applied at the end via fma.
        float r0 = fm * cp0, r1 = fm * cp1, r2 = fm * cp2, r3 = fm * cp3;
        for (int j = 0; j < m; j++) {
            const int q = qlist[j];
            if (q == 0) continue;             // Cv(-1) = 0
            const ushort4 cq =
                *reinterpret_cast<const ushort4*>(&g_cp[b][(q - 1) >> 5][v0]);
            r0 -= (float)cq.x; r1 -= (float)cq.y;
            r2 -= (float)cq.z; r3 -= (float)cq.w;
        }

        // Shared-atomic corrections.
        if (warp == 0) {
            if (lane <= ti)                   // remainder of Cv(t)
                atomicAdd(&acc[srow[t0 + lane]], w2 * fm);
            if (lane == 0)
                atomicAdd(&acc[c], a0 * fm);  // a0 * m at v == c
        }
        for (int j = warp; j < m; j += NW) {  // per-occurrence terms
            const int q = qlist[j];
            if (q > 0) {
                const int s = ((q - 1) & ~(SEG - 1)) + lane;
                if (s <= q - 1) atomicAdd(&acc[srow[s]], -w2);
            }
            if (lane == 0 && q < t)           // bigram c -> next token
                atomicAdd(&acc[srow[q + 1]], a1);
        }
        __syncthreads();                      // acc ready

        // Read + immediately re-zero own acc slots; reset qcnt.
        const float4 av = *reinterpret_cast<const float4*>(&acc[v0]);
        *reinterpret_cast<float4*>(&acc[v0]) = make_float4(0.f, 0.f, 0.f, 0.f);
        if (tid == 0) qcnt = 0;

        float4 a4;
        a4.x = fmaf(w2, r0, av.x);
        a4.y = fmaf(w2, r1, av.y);
        a4.z = fmaf(w2, r2, av.z);
        a4.w = fmaf(w2, r3, av.w);

        // Fused softmax.
        float vmax = fmaxf(fmaxf(a4.x, a4.y), fmaxf(a4.z, a4.w));
        #pragma unroll
        for (int o = 16; o; o >>= 1)
            vmax = fmaxf(vmax, __shfl_xor_sync(0xffffffffu, vmax, o));
        if (lane == 0) rbuf[warp] = vmax;
        __syncthreads();                      // also publishes acc zero + qcnt
        float bmax = rbuf[0];
        #pragma unroll
        for (int w = 1; w < NW; w++) bmax = fmaxf(bmax, rbuf[w]);
        __syncthreads();                      // protect rbuf before reuse

        const float x0 = __expf(a4.x - bmax);
        const float x1 = __expf(a4.y - bmax);
        const float x2 = __expf(a4.z - bmax);
        const float x3 = __expf(a4.w - bmax);
        float ssum = (x0 + x1) + (x2 + x3);
        #pragma unroll
        for (int o = 16; o; o >>= 1)
            ssum += __shfl_xor_sync(0xffffffffu, ssum, o);
        if (lane == 0) rbuf[warp] = ssum;
        __syncthreads();
        float bs = 0.f;
        #pragma unroll
        for (int w = 0; w < NW; w++) bs += rbuf[w];

        const float inv = 1.0f / bs;
        *reinterpret_cast<float4*>(orow + (size_t)ti * V) =
            make_float4(x0 * inv, x1 * inv, x2 * inv, x3 * inv);
    }
}

extern "C" void kernel_launch(void* const* d_in, const int* in_sizes, int n_in,
                              void* d_out, int out_size) {
    const int*   idx = (const int*)d_in[0];
    const float* vw  = (const float*)d_in[1];
    float*       out = (float*)d_out;
    (void)in_sizes; (void)n_in; (void)out_size;

    k_seghist<<<dim3(NSEG, B), NT>>>(idx);
    k_prefix<<<dim3(B, V / NT), NT>>>();
    k_main<<<dim3(NSEG, B), NT>>>(vw, out);
}

// round 4
// speedup vs baseline: 1.8434x; 1.8434x over previous
#include <cuda_runtime.h>

// B=8, T=2048, V=1024.
// c = idx[b,t]; q_1..q_m = occurrences of c in [0..t]; Cv(r) = inclusive prefix
// histogram. Then
//   L_t[v] = w2*( m*Cv(t) - sum_j Cv(q_j-1) ) + a0*m*[v==c]
//            + a1*#{j : q_j+1 <= t, idx(q_j+1)==v},   out = softmax(L_t).
// Cv checkpointed every 32 positions (u16, L2-resident); occurrences stored in
// a CSR list per (b, token). k4: one WARP per t, no block barriers.

namespace {
constexpr int B = 8, T = 2048, V = 1024;
constexpr int SEG = 32, NSEG = T / SEG;
}

__device__ __align__(16) unsigned short g_cp[B][NSEG][V];  // excl. checkpoint
__device__ __align__(16) unsigned short g_row[B][T];
__device__ __align__(16) unsigned short g_off[B][V];       // CSR offsets
__device__ __align__(16) unsigned short g_occ[B][T];       // CSR positions

// ---- K1: segment counts via match_any (g_cp pre-zeroed by memset) ----
__global__ __launch_bounds__(256) void k1_hist(const int* __restrict__ idx) {
    const int b = blockIdx.y;
    const int s = blockIdx.x * 256 + threadIdx.x;
    const int lane = threadIdx.x & 31;
    const unsigned tok = (unsigned)idx[b * T + s];
    g_row[b][s] = (unsigned short)tok;
    const unsigned mask = __match_any_sync(0xffffffffu, tok);
    const unsigned lt = (1u << lane) - 1u;
    if ((mask & lt) == 0u)   // leader lane for this token in this segment
        g_cp[b][s >> 5][tok] = (unsigned short)__popc(mask);
}

// ---- K2: in-place exclusive prefix over segments + CSR offsets ----
__global__ __launch_bounds__(256) void k2_prefix() {
    __shared__ unsigned wsum[8];
    const int b = blockIdx.x;
    const int tid = threadIdx.x, lane = tid & 31, warp = tid >> 5;
    const int v0 = tid * 4;
    unsigned r0 = 0, r1 = 0, r2 = 0, r3 = 0;
    #pragma unroll 8
    for (int k = 0; k < NSEG; k++) {
        ushort4* p = reinterpret_cast<ushort4*>(&g_cp[b][k][v0]);
        const ushort4 x = *p;
        *p = make_ushort4((unsigned short)r0, (unsigned short)r1,
                          (unsigned short)r2, (unsigned short)r3);
        r0 += x.x; r1 += x.y; r2 += x.z; r3 += x.w;
    }
    // exclusive scan of per-thread totals -> CSR offsets
    const unsigned S = r0 + r1 + r2 + r3;
    unsigned incl = S;
    #pragma unroll
    for (int o = 1; o < 32; o <<= 1) {
        unsigned n = __shfl_up_sync(0xffffffffu, incl, o);
        if (lane >= o) incl += n;
    }
    if (lane == 31) wsum[warp] = incl;
    __syncthreads();
    unsigned wex = 0;
    #pragma unroll
    for (int w = 0; w < 8; w++)
        if (w < warp) wex += wsum[w];
    const unsigned base = wex + incl - S;
    ushort4 o4;
    o4.x = (unsigned short)base;
    o4.y = (unsigned short)(base + r0);
    o4.z = (unsigned short)(base + r0 + r1);
    o4.w = (unsigned short)(base + r0 + r1 + r2);
    *reinterpret_cast<ushort4*>(&g_off[b][v0]) = o4;
}

// ---- K3: fill CSR occurrence list (sorted by construction) ----
__global__ __launch_bounds__(256) void k3_fill(const int* __restrict__ idx) {
    const int b = blockIdx.y;
    const int s = blockIdx.x * 256 + threadIdx.x;
    const int lane = threadIdx.x & 31;
    const unsigned tok = (unsigned)idx[b * T + s];
    const unsigned mask = __match_any_sync(0xffffffffu, tok);
    const unsigned lt = (1u << lane) - 1u;
    const int rank = __popc(mask & lt);
    const int slot = (int)g_off[b][tok] + (int)g_cp[b][s >> 5][tok] + rank;
    g_occ[b][slot] = (unsigned short)s;
}

// ---- K4: one warp per t; 4 warps/block, 4 t's per warp; no block barriers ----
__global__ __launch_bounds__(128) void k4_main(const float* __restrict__ vw,
                                               float* __restrict__ out) {
    __shared__ float acc[4][1024];          // warp-private bins
    const int b = blockIdx.y;
    const int t_base = blockIdx.x * 16;     // 16 t's per block, same segment
    const int p = t_base >> 5;
    const int seg0 = p << 5;
    const int tid = threadIdx.x, lane = tid & 31, warp = tid >> 5;
    float* const wacc = acc[warp];
    const int voff = lane * 4;              // lane owns v = k*128 + voff + 0..3

    #pragma unroll
    for (int k = 0; k < 8; k++)
        *reinterpret_cast<float4*>(&wacc[k * 128 + voff]) =
            make_float4(0.f, 0.f, 0.f, 0.f);

    const unsigned stok = g_row[b][seg0 + lane];
    const float w0 = vw[0], w1 = vw[1], w2 = vw[2];
    const float a0 = w0 - w2, a1 = w1 - w2;
    const unsigned short* const cprow_p = &g_cp[b][p][0];
    __syncwarp();

    for (int i = 0; i < 4; i++) {
        const int t = t_base + warp * 4 + i;
        const int ti = t - seg0;            // 0..31
        const unsigned c = __shfl_sync(0xffffffffu, stok, ti);
        const unsigned ball = __ballot_sync(0xffffffffu, stok == c);
        const int m = (int)g_cp[b][p][c] + __popc(ball & ((2u << ti) - 1u));
        const int offc = g_off[b][c];
        const float fm = (float)m;
        const bool fast = (m <= 31);        // m*CP <= 31*2048 < 2^16: packed safe
        const unsigned mu = fast ? (unsigned)m : 0u;

        // Packed 2xu16 SIMD accumulator: pa = m*CP[p] - sum_j CP[(q_j-1)>>5].
        unsigned pa[16];
        #pragma unroll
        for (int k = 0; k < 8; k++) {
            const uint2 w =
                *reinterpret_cast<const uint2*>(cprow_p + k * 128 + voff);
            pa[2 * k]     = mu * w.x;       // m*lo + (m*hi)<<16, no carries
            pa[2 * k + 1] = mu * w.y;
        }

        for (int jb = 0; jb < m; jb += 32) {
            const int nj = min(32, m - jb);
            unsigned qv = 0;
            if (lane < nj) qv = g_occ[b][offc + jb + lane];
            for (int j = 0; j < nj; j++) {
                const int q = __shfl_sync(0xffffffffu, qv, j);
                if (q > 0) {
                    const int qm1 = q - 1, qp = qm1 >> 5;
                    if (fast) {
                        const unsigned short* rowq = &g_cp[b][qp][0];
                        #pragma unroll
                        for (int k = 0; k < 8; k++) {
                            const uint2 w = *reinterpret_cast<const uint2*>(
                                rowq + k * 128 + voff);
                            pa[2 * k]     -= w.x;
                            pa[2 * k + 1] -= w.y;
                        }
                    }
                    // sub-checkpoint remainder of Cv(q-1)
                    const unsigned rtok = g_row[b][(qp << 5) + lane];
                    if (lane <= (qm1 & 31))
                        atomicAdd(&wacc[rtok], -w2);
                }
                if (q < t && lane == 0) {   // bigram c -> next token
                    const unsigned nt = g_row[b][q + 1];
                    atomicAdd(&wacc[nt], a1);
                }
            }
        }

        if (!fast) {  // exact cold path for m > 31 (overflow-safe, i32)
            #pragma unroll 1
            for (int k = 0; k < 8; k++) {
                const uint2 w =
                    *reinterpret_cast<const uint2*>(cprow_p + k * 128 + voff);
                int l0 = m * (int)(w.x & 0xffffu);
                int l1 = m * (int)(w.x >> 16);
                int l2 = m * (int)(w.y & 0xffffu);
                int l3 = m * (int)(w.y >> 16);
                for (int j = 0; j < m; j++) {
                    const int q = g_occ[b][offc + j];
                    if (q > 0) {
                        const uint2 u = *reinterpret_cast<const uint2*>(
                            &g_cp[b][(q - 1) >> 5][0] + k * 128 + voff);
                        l0 -= (int)(u.x & 0xffffu); l1 -= (int)(u.x >> 16);
                        l2 -= (int)(u.y & 0xffffu); l3 -= (int)(u.y >> 16);
                    }
                }
                atomicAdd(&wacc[k * 128 + voff + 0], w2 * (float)l0);
                atomicAdd(&wacc[k * 128 + voff + 1], w2 * (float)l1);
                atomicAdd(&wacc[k * 128 + voff + 2], w2 * (float)l2);
                atomicAdd(&wacc[k * 128 + voff + 3], w2 * (float)l3);
            }
        }

        // remainder of Cv(t) over this segment + a0 term
        if (lane <= ti) atomicAdd(&wacc[stok], w2 * fm);
        if (lane == ti) atomicAdd(&wacc[c], a0 * fm);
        __syncwarp();

        // assemble logits (unpack packed counts), warp-local softmax
        float a[32];
        float vmax = -3.0e38f;
        #pragma unroll
        for (int k = 0; k < 8; k++) {
            const float4 av =
                *reinterpret_cast<const float4*>(&wacc[k * 128 + voff]);
            *reinterpret_cast<float4*>(&wacc[k * 128 + voff]) =
                make_float4(0.f, 0.f, 0.f, 0.f);  // re-zero for next t
            a[4 * k + 0] = fmaf(w2, (float)(pa[2 * k] & 0xffffu),     av.x);
            a[4 * k + 1] = fmaf(w2, (float)(pa[2 * k] >> 16),         av.y);
            a[4 * k + 2] = fmaf(w2, (float)(pa[2 * k + 1] & 0xffffu), av.z);
            a[4 * k + 3] = fmaf(w2, (float)(pa[2 * k + 1] >> 16),     av.w);
            vmax = fmaxf(vmax, fmaxf(fmaxf(a[4 * k], a[4 * k + 1]),
                                     fmaxf(a[4 * k + 2], a[4 * k + 3])));
        }
        #pragma unroll
        for (int o = 16; o; o >>= 1)
            vmax = fmaxf(vmax, __shfl_xor_sync(0xffffffffu, vmax, o));

        float ssum = 0.f;
        #pragma unroll
        for (int k = 0; k < 32; k++) {
            a[k] = __expf(a[k] - vmax);
            ssum += a[k];
        }
        #pragma unroll
        for (int o = 16; o; o >>= 1)
            ssum += __shfl_xor_sync(0xffffffffu, ssum, o);
        const float inv = 1.0f / ssum;

        float* const orow = out + (size_t)(b * T + t) * V + voff;
        #pragma unroll
        for (int k = 0; k < 8; k++)
            *reinterpret_cast<float4*>(orow + k * 128) =
                make_float4(a[4 * k] * inv, a[4 * k + 1] * inv,
                            a[4 * k + 2] * inv, a[4 * k + 3] * inv);

        __syncwarp();   // acc re-zero visible before next t's atomics
    }
}

extern "C" void kernel_launch(void* const* d_in, const int* in_sizes, int n_in,
                              void* d_out, int out_size) {
    const int*   idx = (const int*)d_in[0];
    const float* vw  = (const float*)d_in[1];
    float*       out = (float*)d_out;
    (void)in_sizes; (void)n_in; (void)out_size;

    void* cp_ptr = nullptr;
    cudaGetSymbolAddress(&cp_ptr, g_cp);
    cudaMemsetAsync(cp_ptr, 0, (size_t)B * NSEG * V * sizeof(unsigned short));

    k1_hist <<<dim3(T / 256, B), 256>>>(idx);
    k2_prefix<<<dim3(B), 256>>>();
    k3_fill <<<dim3(T / 256, B), 256>>>(idx);
    k4_main <<<dim3(T / 16, B), 128>>>(vw, out);
}